// round 6
// baseline (speedup 1.0000x reference)
#include <cuda_runtime.h>

// ---------------------------------------------------------------------------
// GATv2 block — algebraically reduced implementation.
//
// Identities:
//   Sum_e alpha_e = 1 per destination node with >=1 incoming edge (denom >= 1,
//   the +1e-16 vanishes below fp32 ULP), and agg gathers nodes[R] which is
//   constant within a segment:
//     agg[n] = flag[n] * (x[n]@W_n + b_n)
//   x_new = relu( flag * (x@W_c + b_c) + G2[batch] )
//       W_c = W_n @ W_n2[0:128],  b_c = b_n @ W_n2[0:128]
//       G2[b] = glob[b] @ W_n2[128:192] + b_n2
//   e_new = relu( P[L] + edge_attr @ W_e[128:192] ),  P = x@W_e[0:128] + b_e
//   g_new = relu( [glob, segment_mean(x_new)] @ W_g + b_g )
// W_le, b_le, a are dead w.r.t. all outputs.
//
// Indices (edge_index, batch) are int32 per the harness dtype contract.
// All data-derived indices are clamped defensively.
// ---------------------------------------------------------------------------

#define MAX_N 50000

// scratch (device globals; allocation is forbidden). 16B-aligned (float4 use).
__device__ __align__(16) float d_P[MAX_N * 128];   // x @ W_e_top + b_e
__device__ __align__(16) float d_Wc[128 * 128];    // W_n @ W_n2_top
__device__ __align__(16) float d_bc[128];          // b_n @ W_n2_top
__device__ __align__(16) float d_G2[64 * 128];     // glob @ W_n2_bot + b_n2
__device__ int d_flags[MAX_N];                     // has-incoming-edge flag

__device__ __forceinline__ int clampi(int v, int lo, int hi) {
    return v < lo ? lo : (v > hi ? hi : v);
}

// ---------------------------------------------------------------------------
__global__ void flags_zero_kernel(int n) {
    int i = blockIdx.x * blockDim.x + threadIdx.x;
    if (i < n) d_flags[i] = 0;
}

__global__ void flags_set_kernel(const int* __restrict__ eidx, int E, int N) {
    int e = blockIdx.x * blockDim.x + threadIdx.x;
    if (e < E) {
        int r = eidx[E + e];  // edge_index[1][e] (destination)
        if ((unsigned)r < (unsigned)N) d_flags[r] = 1;
    }
}

// grid = 128 (W_c rows) + 1 (b_c) + B (G2 rows); 128 threads
__global__ void precompute_kernel(const float* __restrict__ W_n,
                                  const float* __restrict__ b_n,
                                  const float* __restrict__ W_n2,
                                  const float* __restrict__ b_n2,
                                  const float* __restrict__ glob) {
    int blk = blockIdx.x;
    int j = threadIdx.x;  // 0..127
    if (blk < 128) {
        __shared__ float wr[128];
        wr[j] = W_n[blk * 128 + j];
        __syncthreads();
        float acc = 0.f;
#pragma unroll 8
        for (int k = 0; k < 128; ++k) acc = fmaf(wr[k], W_n2[k * 128 + j], acc);
        d_Wc[blk * 128 + j] = acc;
    } else if (blk == 128) {
        float acc = 0.f;
        for (int k = 0; k < 128; ++k) acc = fmaf(b_n[k], W_n2[k * 128 + j], acc);
        d_bc[j] = acc;
    } else {
        int b = blk - 129;
        float acc = b_n2[j];
        for (int k = 0; k < 64; ++k)
            acc = fmaf(glob[b * 64 + k], W_n2[(128 + k) * 128 + j], acc);
        d_G2[b * 128 + j] = acc;
    }
}

// ---------------------------------------------------------------------------
// Node kernel: per 64-node tile, one (64x128)@(128x256) GEMM.
//   output cols 0..127   -> P (x@W_e_top + b_e)   -> d_P
//   output cols 128..255 -> x_new epilogue (flag, +b_c, +G2[batch], relu)
// 256 threads: r = tid>>6 (0..3) owns 16 nodes; c = tid&63 owns 4 cols.
// Warp-uniform weight source: warps with c<32 read W_e, c>=32 read d_Wc.
// Weights stream from global (L2-resident, 128KB). smem: x tile only (32KB).
__global__ __launch_bounds__(256) void node_kernel(
    const float* __restrict__ x, const float* __restrict__ W_e,
    const float* __restrict__ b_e, const int* __restrict__ batch,
    float* __restrict__ xnew, int nNodes, int nGraphs)
{
    __shared__ __align__(16) float xs[64 * 128];   // 32 KB
    const int tid = threadIdx.x;
    const int n0 = blockIdx.x * 64;

    const float4* x4 = reinterpret_cast<const float4*>(x);
    float4* xs4w = reinterpret_cast<float4*>(xs);
    for (int idx = tid; idx < 64 * 32; idx += 256) {
        int node = idx >> 5, kk = idx & 31;
        int gn = n0 + node;
        xs4w[idx] = (gn < nNodes) ? x4[(size_t)gn * 32 + kk]
                                  : make_float4(0.f, 0.f, 0.f, 0.f);
    }
    __syncthreads();

    const int r = tid >> 6;
    const int c = tid & 63;

    // weight pointer: 4 output cols (one float4) per k-row, row stride 32 f4
    const float4* wp = (c < 32)
        ? reinterpret_cast<const float4*>(W_e) + c
        : reinterpret_cast<const float4*>(d_Wc) + (c - 32);

    float acc[16][4];
#pragma unroll
    for (int i = 0; i < 16; ++i) {
        acc[i][0] = 0.f; acc[i][1] = 0.f; acc[i][2] = 0.f; acc[i][3] = 0.f;
    }

    const float4* xs4 = reinterpret_cast<const float4*>(xs);  // [64][32]

#pragma unroll 4
    for (int k4 = 0; k4 < 32; ++k4) {
        float4 w0 = wp[(k4 * 4 + 0) * 32];
        float4 w1 = wp[(k4 * 4 + 1) * 32];
        float4 w2 = wp[(k4 * 4 + 2) * 32];
        float4 w3 = wp[(k4 * 4 + 3) * 32];
#pragma unroll
        for (int i = 0; i < 16; ++i) {
            float4 xv = xs4[(r * 16 + i) * 32 + k4];
            acc[i][0] = fmaf(xv.x, w0.x, acc[i][0]);
            acc[i][1] = fmaf(xv.x, w0.y, acc[i][1]);
            acc[i][2] = fmaf(xv.x, w0.z, acc[i][2]);
            acc[i][3] = fmaf(xv.x, w0.w, acc[i][3]);
            acc[i][0] = fmaf(xv.y, w1.x, acc[i][0]);
            acc[i][1] = fmaf(xv.y, w1.y, acc[i][1]);
            acc[i][2] = fmaf(xv.y, w1.z, acc[i][2]);
            acc[i][3] = fmaf(xv.y, w1.w, acc[i][3]);
            acc[i][0] = fmaf(xv.z, w2.x, acc[i][0]);
            acc[i][1] = fmaf(xv.z, w2.y, acc[i][1]);
            acc[i][2] = fmaf(xv.z, w2.z, acc[i][2]);
            acc[i][3] = fmaf(xv.z, w2.w, acc[i][3]);
            acc[i][0] = fmaf(xv.w, w3.x, acc[i][0]);
            acc[i][1] = fmaf(xv.w, w3.y, acc[i][1]);
            acc[i][2] = fmaf(xv.w, w3.z, acc[i][2]);
            acc[i][3] = fmaf(xv.w, w3.w, acc[i][3]);
        }
    }

    if (c < 32) {
        // P columns (j = 4c .. 4c+3), + b_e
        const float4 bev = reinterpret_cast<const float4*>(b_e)[c];
        float4* P4 = reinterpret_cast<float4*>(d_P);
#pragma unroll
        for (int i = 0; i < 16; ++i) {
            int gn = n0 + r * 16 + i;
            if (gn < nNodes) {
                P4[(size_t)gn * 32 + c] =
                    make_float4(acc[i][0] + bev.x, acc[i][1] + bev.y,
                                acc[i][2] + bev.z, acc[i][3] + bev.w);
            }
        }
    } else {
        // x_new columns
        const int cc = c - 32;
        const float4 bcv = reinterpret_cast<const float4*>(d_bc)[cc];
        const float4* G24 = reinterpret_cast<const float4*>(d_G2);
        float4* out4 = reinterpret_cast<float4*>(xnew);
#pragma unroll
        for (int i = 0; i < 16; ++i) {
            int gn = n0 + r * 16 + i;
            if (gn < nNodes) {
                int fl = d_flags[gn];
                int b = clampi(batch[gn], 0, nGraphs - 1);
                float4 g2 = G24[b * 32 + cc];
                float4 v;
                v.x = (fl ? acc[i][0] + bcv.x : 0.f) + g2.x;
                v.y = (fl ? acc[i][1] + bcv.y : 0.f) + g2.y;
                v.z = (fl ? acc[i][2] + bcv.z : 0.f) + g2.z;
                v.w = (fl ? acc[i][3] + bcv.w : 0.f) + g2.w;
                v.x = fmaxf(v.x, 0.f); v.y = fmaxf(v.y, 0.f);
                v.z = fmaxf(v.z, 0.f); v.w = fmaxf(v.w, 0.f);
                out4[(size_t)gn * 32 + cc] = v;
            }
        }
    }
}

// ---------------------------------------------------------------------------
// Edge kernel: e_new = relu(P[L] + edge_attr @ W_e[128:192]).
// Tile: 64 edges x 128 cols, K=64. 256 threads: r = tid>>5 (0..7) owns 8
// edges; c = tid&31 owns 4 cols. Weights (32KB) stream from L2.
// smem: edge_attr tile only (16KB).
__global__ __launch_bounds__(256) void edge_kernel(
    const float* __restrict__ edge_attr, const int* __restrict__ eidx,
    const float* __restrict__ W_e, float* __restrict__ enew, int E, int nNodes)
{
    __shared__ __align__(16) float es[64 * 64];    // 16 KB
    const int tid = threadIdx.x;
    const int e0 = blockIdx.x * 64;

    const float4* ea4 = reinterpret_cast<const float4*>(edge_attr);
    float4* es4w = reinterpret_cast<float4*>(es);
    for (int idx = tid; idx < 64 * 16; idx += 256) {
        int e = idx >> 4, kk = idx & 15;
        int ge = e0 + e;
        es4w[idx] = (ge < E) ? ea4[(size_t)ge * 16 + kk]
                             : make_float4(0.f, 0.f, 0.f, 0.f);
    }
    __syncthreads();

    const int r = tid >> 5;
    const int c = tid & 31;

    // W_e rows 128..191 (edge_attr half): float offset 128*128 = f4 offset 4096
    const float4* wp = reinterpret_cast<const float4*>(W_e) + 4096 + c;

    float acc[8][4];
#pragma unroll
    for (int i = 0; i < 8; ++i) {
        acc[i][0] = 0.f; acc[i][1] = 0.f; acc[i][2] = 0.f; acc[i][3] = 0.f;
    }

    const float4* es4 = reinterpret_cast<const float4*>(es);  // [64][16]

#pragma unroll 4
    for (int k4 = 0; k4 < 16; ++k4) {
        float4 w0 = wp[(k4 * 4 + 0) * 32];
        float4 w1 = wp[(k4 * 4 + 1) * 32];
        float4 w2 = wp[(k4 * 4 + 2) * 32];
        float4 w3 = wp[(k4 * 4 + 3) * 32];
#pragma unroll
        for (int i = 0; i < 8; ++i) {
            float4 ev = es4[(r * 8 + i) * 16 + k4];
            acc[i][0] = fmaf(ev.x, w0.x, acc[i][0]);
            acc[i][1] = fmaf(ev.x, w0.y, acc[i][1]);
            acc[i][2] = fmaf(ev.x, w0.z, acc[i][2]);
            acc[i][3] = fmaf(ev.x, w0.w, acc[i][3]);
            acc[i][0] = fmaf(ev.y, w1.x, acc[i][0]);
            acc[i][1] = fmaf(ev.y, w1.y, acc[i][1]);
            acc[i][2] = fmaf(ev.y, w1.z, acc[i][2]);
            acc[i][3] = fmaf(ev.y, w1.w, acc[i][3]);
            acc[i][0] = fmaf(ev.z, w2.x, acc[i][0]);
            acc[i][1] = fmaf(ev.z, w2.y, acc[i][1]);
            acc[i][2] = fmaf(ev.z, w2.z, acc[i][2]);
            acc[i][3] = fmaf(ev.z, w2.w, acc[i][3]);
            acc[i][0] = fmaf(ev.w, w3.x, acc[i][0]);
            acc[i][1] = fmaf(ev.w, w3.y, acc[i][1]);
            acc[i][2] = fmaf(ev.w, w3.z, acc[i][2]);
            acc[i][3] = fmaf(ev.w, w3.w, acc[i][3]);
        }
    }

    const float4* P4 = reinterpret_cast<const float4*>(d_P);
    float4* out4 = reinterpret_cast<float4*>(enew);
#pragma unroll
    for (int i = 0; i < 8; ++i) {
        int ge = e0 + r * 8 + i;
        if (ge < E) {
            int L = clampi(eidx[ge], 0, nNodes - 1);  // edge_index[0][ge]
            float4 p = P4[(size_t)L * 32 + c];
            out4[(size_t)ge * 32 + c] =
                make_float4(fmaxf(acc[i][0] + p.x, 0.f),
                            fmaxf(acc[i][1] + p.y, 0.f),
                            fmaxf(acc[i][2] + p.z, 0.f),
                            fmaxf(acc[i][3] + p.w, 0.f));
        }
    }
}

// ---------------------------------------------------------------------------
// Global kernel: one block (128 thr) per graph. batch is sorted -> binary
// search segment bounds, segment mean of x_new, then
// g_new = relu([glob, mean] @ W_g + b_g).
__global__ void global_kernel(const float* __restrict__ xnew,
                              const int* __restrict__ batch,
                              const float* __restrict__ glob,
                              const float* __restrict__ W_g,
                              const float* __restrict__ b_g,
                              float* __restrict__ gout, int nNodes)
{
    const int b = blockIdx.x;
    const int tid = threadIdx.x;  // 128 threads

    int lo = 0, hi = nNodes;
    while (lo < hi) { int mid = (lo + hi) >> 1; if (batch[mid] < b) lo = mid + 1; else hi = mid; }
    int s = lo;
    lo = s; hi = nNodes;
    while (lo < hi) { int mid = (lo + hi) >> 1; if (batch[mid] < b + 1) lo = mid + 1; else hi = mid; }
    int e2 = lo;

    float sum = 0.f;
    for (int row = s; row < e2; ++row) sum += xnew[(size_t)row * 128 + tid];

    __shared__ float mean_s[128];
    __shared__ float glob_s[64];
    float cnt = fmaxf((float)(e2 - s), 1.0f);
    mean_s[tid] = sum / cnt;
    if (tid < 64) glob_s[tid] = glob[b * 64 + tid];
    __syncthreads();

    if (tid < 64) {
        float acc = b_g[tid];
        for (int k = 0; k < 64; ++k)  acc = fmaf(glob_s[k], W_g[k * 64 + tid], acc);
        for (int k = 0; k < 128; ++k) acc = fmaf(mean_s[k], W_g[(64 + k) * 64 + tid], acc);
        gout[b * 64 + tid] = fmaxf(acc, 0.f);
    }
}

// ---------------------------------------------------------------------------
extern "C" void kernel_launch(void* const* d_in, const int* in_sizes, int n_in,
                              void* d_out, int out_size) {
    const float* x         = (const float*)d_in[0];
    const int*   eidx      = (const int*)d_in[1];     // int32 per harness contract
    const float* edge_attr = (const float*)d_in[2];
    const float* glob      = (const float*)d_in[3];
    const int*   batch     = (const int*)d_in[4];     // int32 per harness contract
    const float* W_e       = (const float*)d_in[5];
    const float* b_e       = (const float*)d_in[6];
    // d_in[7] = W_le, d_in[8] = b_le -- dead w.r.t. outputs
    const float* W_n       = (const float*)d_in[9];
    const float* b_n       = (const float*)d_in[10];
    const float* W_n2      = (const float*)d_in[11];
    const float* b_n2      = (const float*)d_in[12];
    const float* W_g       = (const float*)d_in[13];
    const float* b_g       = (const float*)d_in[14];
    // d_in[15] = a -- dead

    const int N = in_sizes[0] / 128;
    const int E = in_sizes[1] / 2;
    const int B = in_sizes[3] / 64;

    float* xnew = (float*)d_out;               // [N,128]
    float* enew = xnew + (size_t)N * 128;      // [E,128]
    float* gnew = enew + (size_t)E * 128;      // [B,64]

    flags_zero_kernel<<<(N + 255) / 256, 256>>>(N);
    flags_set_kernel<<<(E + 255) / 256, 256>>>(eidx, E, N);
    precompute_kernel<<<129 + B, 128>>>(W_n, b_n, W_n2, b_n2, glob);
    node_kernel<<<(N + 63) / 64, 256>>>(x, W_e, b_e, batch, xnew, N, B);
    edge_kernel<<<(E + 63) / 64, 256>>>(edge_attr, eidx, W_e, enew, E, N);
    global_kernel<<<B, 128>>>(xnew, batch, glob, W_g, b_g, gnew, N);
}

// round 7
// speedup vs baseline: 1.3291x; 1.3291x over previous
#include <cuda_runtime.h>

// ---------------------------------------------------------------------------
// GATv2 block — algebraically reduced; edge GEMM on tensor cores (tf32 mma).
//
// Identities:
//   Sum_e alpha_e = 1 per destination node with >=1 incoming edge, and agg
//   gathers nodes[R] (constant within a segment):
//     agg[n] = flag[n] * (x[n]@W_n + b_n)
//   x_new = relu( flag * (x@W_c + b_c) + G2[batch] )     (exact fp32)
//   e_new = relu( P[L] + edge_attr @ W_e[128:192] )       (tf32 mma + fp32 P)
//       P  = x@W_e[0:128] + b_e                           (exact fp32)
//   g_new = relu( [glob, segment_mean(x_new)] @ W_g + b_g )
// W_le, b_le, a are dead w.r.t. all outputs.
// ---------------------------------------------------------------------------

#define MAX_N 50000

__device__ __align__(16) float d_P[MAX_N * 128];   // x @ W_e_top + b_e
__device__ __align__(16) float d_Wc[128 * 128];    // W_n @ W_n2_top
__device__ __align__(16) float d_bc[128];          // b_n @ W_n2_top
__device__ __align__(16) float d_G2[64 * 128];     // glob @ W_n2_bot + b_n2
__device__ int d_flags[MAX_N];

__device__ __forceinline__ int clampi(int v, int lo, int hi) {
    return v < lo ? lo : (v > hi ? hi : v);
}

__device__ __forceinline__ float to_tf32(float x) {
    float r;
    asm("cvt.rna.tf32.f32 %0, %1;" : "=f"(r) : "f"(x));
    return r;
}

// ---------------------------------------------------------------------------
__global__ void flags_zero_kernel(int n) {
    int i = blockIdx.x * blockDim.x + threadIdx.x;
    if (i < n) d_flags[i] = 0;
}

__global__ void flags_set_kernel(const int* __restrict__ eidx, int E, int N) {
    int e = blockIdx.x * blockDim.x + threadIdx.x;
    if (e < E) {
        int r = eidx[E + e];  // edge_index[1][e] (destination)
        if ((unsigned)r < (unsigned)N) d_flags[r] = 1;
    }
}

// grid = 128 (W_c rows) + 1 (b_c) + B (G2 rows); 128 threads
__global__ void precompute_kernel(const float* __restrict__ W_n,
                                  const float* __restrict__ b_n,
                                  const float* __restrict__ W_n2,
                                  const float* __restrict__ b_n2,
                                  const float* __restrict__ glob) {
    int blk = blockIdx.x;
    int j = threadIdx.x;  // 0..127
    if (blk < 128) {
        __shared__ float wr[128];
        wr[j] = W_n[blk * 128 + j];
        __syncthreads();
        float acc = 0.f;
#pragma unroll 8
        for (int k = 0; k < 128; ++k) acc = fmaf(wr[k], W_n2[k * 128 + j], acc);
        d_Wc[blk * 128 + j] = acc;
    } else if (blk == 128) {
        float acc = 0.f;
        for (int k = 0; k < 128; ++k) acc = fmaf(b_n[k], W_n2[k * 128 + j], acc);
        d_bc[j] = acc;
    } else {
        int b = blk - 129;
        float acc = b_n2[j];
        for (int k = 0; k < 64; ++k)
            acc = fmaf(glob[b * 64 + k], W_n2[(128 + k) * 128 + j], acc);
        d_G2[b * 128 + j] = acc;
    }
}

// ---------------------------------------------------------------------------
// Node kernel (exact fp32): per 64-node tile, (64x128)@(128x256) GEMM.
//   cols 0..127   -> P   -> d_P
//   cols 128..255 -> x_new epilogue (flag, +b_c, +G2[batch], relu)
__global__ __launch_bounds__(256) void node_kernel(
    const float* __restrict__ x, const float* __restrict__ W_e,
    const float* __restrict__ b_e, const int* __restrict__ batch,
    float* __restrict__ xnew, int nNodes, int nGraphs)
{
    __shared__ __align__(16) float xs[64 * 128];   // 32 KB
    const int tid = threadIdx.x;
    const int n0 = blockIdx.x * 64;

    const float4* x4 = reinterpret_cast<const float4*>(x);
    float4* xs4w = reinterpret_cast<float4*>(xs);
    for (int idx = tid; idx < 64 * 32; idx += 256) {
        int node = idx >> 5, kk = idx & 31;
        int gn = n0 + node;
        xs4w[idx] = (gn < nNodes) ? x4[(size_t)gn * 32 + kk]
                                  : make_float4(0.f, 0.f, 0.f, 0.f);
    }
    __syncthreads();

    const int r = tid >> 6;
    const int c = tid & 63;

    const float4* wp = (c < 32)
        ? reinterpret_cast<const float4*>(W_e) + c
        : reinterpret_cast<const float4*>(d_Wc) + (c - 32);

    float acc[16][4];
#pragma unroll
    for (int i = 0; i < 16; ++i) {
        acc[i][0] = 0.f; acc[i][1] = 0.f; acc[i][2] = 0.f; acc[i][3] = 0.f;
    }

    const float4* xs4 = reinterpret_cast<const float4*>(xs);  // [64][32]

#pragma unroll 4
    for (int k4 = 0; k4 < 32; ++k4) {
        float4 w0 = wp[(k4 * 4 + 0) * 32];
        float4 w1 = wp[(k4 * 4 + 1) * 32];
        float4 w2 = wp[(k4 * 4 + 2) * 32];
        float4 w3 = wp[(k4 * 4 + 3) * 32];
#pragma unroll
        for (int i = 0; i < 16; ++i) {
            float4 xv = xs4[(r * 16 + i) * 32 + k4];
            acc[i][0] = fmaf(xv.x, w0.x, acc[i][0]);
            acc[i][1] = fmaf(xv.x, w0.y, acc[i][1]);
            acc[i][2] = fmaf(xv.x, w0.z, acc[i][2]);
            acc[i][3] = fmaf(xv.x, w0.w, acc[i][3]);
            acc[i][0] = fmaf(xv.y, w1.x, acc[i][0]);
            acc[i][1] = fmaf(xv.y, w1.y, acc[i][1]);
            acc[i][2] = fmaf(xv.y, w1.z, acc[i][2]);
            acc[i][3] = fmaf(xv.y, w1.w, acc[i][3]);
            acc[i][0] = fmaf(xv.z, w2.x, acc[i][0]);
            acc[i][1] = fmaf(xv.z, w2.y, acc[i][1]);
            acc[i][2] = fmaf(xv.z, w2.z, acc[i][2]);
            acc[i][3] = fmaf(xv.z, w2.w, acc[i][3]);
            acc[i][0] = fmaf(xv.w, w3.x, acc[i][0]);
            acc[i][1] = fmaf(xv.w, w3.y, acc[i][1]);
            acc[i][2] = fmaf(xv.w, w3.z, acc[i][2]);
            acc[i][3] = fmaf(xv.w, w3.w, acc[i][3]);
        }
    }

    if (c < 32) {
        const float4 bev = reinterpret_cast<const float4*>(b_e)[c];
        float4* P4 = reinterpret_cast<float4*>(d_P);
#pragma unroll
        for (int i = 0; i < 16; ++i) {
            int gn = n0 + r * 16 + i;
            if (gn < nNodes) {
                P4[(size_t)gn * 32 + c] =
                    make_float4(acc[i][0] + bev.x, acc[i][1] + bev.y,
                                acc[i][2] + bev.z, acc[i][3] + bev.w);
            }
        }
    } else {
        const int cc = c - 32;
        const float4 bcv = reinterpret_cast<const float4*>(d_bc)[cc];
        const float4* G24 = reinterpret_cast<const float4*>(d_G2);
        float4* out4 = reinterpret_cast<float4*>(xnew);
#pragma unroll
        for (int i = 0; i < 16; ++i) {
            int gn = n0 + r * 16 + i;
            if (gn < nNodes) {
                int fl = d_flags[gn];
                int b = clampi(batch[gn], 0, nGraphs - 1);
                float4 g2 = G24[b * 32 + cc];
                float4 v;
                v.x = (fl ? acc[i][0] + bcv.x : 0.f) + g2.x;
                v.y = (fl ? acc[i][1] + bcv.y : 0.f) + g2.y;
                v.z = (fl ? acc[i][2] + bcv.z : 0.f) + g2.z;
                v.w = (fl ? acc[i][3] + bcv.w : 0.f) + g2.w;
                v.x = fmaxf(v.x, 0.f); v.y = fmaxf(v.y, 0.f);
                v.z = fmaxf(v.z, 0.f); v.w = fmaxf(v.w, 0.f);
                out4[(size_t)gn * 32 + cc] = v;
            }
        }
    }
}

// ---------------------------------------------------------------------------
// Edge kernel (tf32 tensor cores):
//   e_new = relu( P[L] + edge_attr @ W_e[128:192] )
// Block = 64 edges x 64 cols (col-half h = blockIdx.x & 1). 128 threads,
// 4 warps; each warp computes a m16 x n64 x k64 tile with mma.m16n8k8.tf32.
// smem padded for conflict-free fragment loads:
//   A (edge_attr) stride 68 (68 mod 32 = 4), B (weights) stride 72 (mod 32 = 8).
// P gather + bias + relu in fp32 epilogue.
__global__ __launch_bounds__(128) void edge_kernel(
    const float* __restrict__ edge_attr, const int* __restrict__ eidx,
    const float* __restrict__ W_e, float* __restrict__ enew, int E, int nNodes)
{
    __shared__ __align__(16) float es[64 * 68];   // 17408 B
    __shared__ __align__(16) float Ws[64 * 72];   // 18432 B
    __shared__ int Ls[64];

    const int tid  = threadIdx.x;
    const int tile = blockIdx.x >> 1;
    const int h    = blockIdx.x & 1;        // column half: cols [64h, 64h+64)
    const int e0   = tile * 64;

    if (tid < 64) {
        int ge = e0 + tid;
        Ls[tid] = (ge < E) ? clampi(eidx[ge], 0, nNodes - 1) : 0;
    }

    // A tile: 64 edges x 64 k, tf32-rounded, stride 68
    const float4* ea4 = reinterpret_cast<const float4*>(edge_attr);
#pragma unroll
    for (int it = 0; it < 8; ++it) {
        int idx = tid + it * 128;            // 0..1023
        int e = idx >> 4, kk = idx & 15;
        int ge = e0 + e;
        float4 v = (ge < E) ? ea4[(size_t)ge * 16 + kk]
                            : make_float4(0.f, 0.f, 0.f, 0.f);
        float* d = es + e * 68 + kk * 4;
        d[0] = to_tf32(v.x); d[1] = to_tf32(v.y);
        d[2] = to_tf32(v.z); d[3] = to_tf32(v.w);
    }

    // B tile: W_e rows 128..191, cols [64h, 64h+64), tf32, stride 72
    const float4* W4 = reinterpret_cast<const float4*>(W_e);
#pragma unroll
    for (int it = 0; it < 8; ++it) {
        int idx = tid + it * 128;            // 0..1023
        int k = idx >> 4, kk = idx & 15;
        float4 v = W4[(size_t)(128 + k) * 32 + h * 16 + kk];
        float* d = Ws + k * 72 + kk * 4;
        d[0] = to_tf32(v.x); d[1] = to_tf32(v.y);
        d[2] = to_tf32(v.z); d[3] = to_tf32(v.w);
    }
    __syncthreads();

    const int warp = tid >> 5;
    const int lane = tid & 31;
    const int qr = lane >> 2;     // 0..7
    const int qc = lane & 3;      // 0..3

    float c[8][4];
#pragma unroll
    for (int j = 0; j < 8; ++j) {
        c[j][0] = 0.f; c[j][1] = 0.f; c[j][2] = 0.f; c[j][3] = 0.f;
    }

    const float* arow0 = es + (warp * 16 + qr) * 68;      // rows qr
    const float* arow1 = es + (warp * 16 + qr + 8) * 68;  // rows qr+8

#pragma unroll
    for (int s = 0; s < 8; ++s) {
        const int kb = s * 8;
        float a0 = arow0[kb + qc];
        float a1 = arow1[kb + qc];
        float a2 = arow0[kb + qc + 4];
        float a3 = arow1[kb + qc + 4];
        const float* b0p = Ws + (kb + qc) * 72 + qr;
        const float* b1p = Ws + (kb + 4 + qc) * 72 + qr;
#pragma unroll
        for (int j = 0; j < 8; ++j) {
            float b0 = b0p[8 * j];
            float b1 = b1p[8 * j];
            asm volatile(
                "mma.sync.aligned.m16n8k8.row.col.f32.tf32.tf32.f32 "
                "{%0,%1,%2,%3}, {%4,%5,%6,%7}, {%8,%9}, {%0,%1,%2,%3};"
                : "+f"(c[j][0]), "+f"(c[j][1]), "+f"(c[j][2]), "+f"(c[j][3])
                : "r"(__float_as_uint(a0)), "r"(__float_as_uint(a1)),
                  "r"(__float_as_uint(a2)), "r"(__float_as_uint(a3)),
                  "r"(__float_as_uint(b0)), "r"(__float_as_uint(b1)));
        }
    }

    // Epilogue: + P[L], relu, store. Thread holds D rows (qr, qr+8) of its
    // warp's 16 edges, cols 2*qc, 2*qc+1 within each n-tile j.
    const float2* P2 = reinterpret_cast<const float2*>(d_P);
    float2* out2 = reinterpret_cast<float2*>(enew);
    const int colbase = h * 64 + qc * 2;

#pragma unroll
    for (int half = 0; half < 2; ++half) {
        int eloc = warp * 16 + qr + half * 8;
        int ge = e0 + eloc;
        if (ge < E) {
            int L = Ls[eloc];
            const float2* prow = P2 + (size_t)L * 64;
            float2* orow = out2 + (size_t)ge * 64;
#pragma unroll
            for (int j = 0; j < 8; ++j) {
                int col = colbase + 8 * j;          // even -> float2 aligned
                float2 p = prow[col >> 1];
                float2 v;
                v.x = fmaxf(c[j][half * 2 + 0] + p.x, 0.f);
                v.y = fmaxf(c[j][half * 2 + 1] + p.y, 0.f);
                orow[col >> 1] = v;
            }
        }
    }
}

// ---------------------------------------------------------------------------
// Global kernel: one block (128 thr) per graph; batch sorted -> binary search.
__global__ void global_kernel(const float* __restrict__ xnew,
                              const int* __restrict__ batch,
                              const float* __restrict__ glob,
                              const float* __restrict__ W_g,
                              const float* __restrict__ b_g,
                              float* __restrict__ gout, int nNodes)
{
    const int b = blockIdx.x;
    const int tid = threadIdx.x;  // 128 threads

    int lo = 0, hi = nNodes;
    while (lo < hi) { int mid = (lo + hi) >> 1; if (batch[mid] < b) lo = mid + 1; else hi = mid; }
    int s = lo;
    lo = s; hi = nNodes;
    while (lo < hi) { int mid = (lo + hi) >> 1; if (batch[mid] < b + 1) lo = mid + 1; else hi = mid; }
    int e2 = lo;

    float sum = 0.f;
    for (int row = s; row < e2; ++row) sum += xnew[(size_t)row * 128 + tid];

    __shared__ float mean_s[128];
    __shared__ float glob_s[64];
    float cnt = fmaxf((float)(e2 - s), 1.0f);
    mean_s[tid] = sum / cnt;
    if (tid < 64) glob_s[tid] = glob[b * 64 + tid];
    __syncthreads();

    if (tid < 64) {
        float acc = b_g[tid];
        for (int k = 0; k < 64; ++k)  acc = fmaf(glob_s[k], W_g[k * 64 + tid], acc);
        for (int k = 0; k < 128; ++k) acc = fmaf(mean_s[k], W_g[(64 + k) * 64 + tid], acc);
        gout[b * 64 + tid] = fmaxf(acc, 0.f);
    }
}

// ---------------------------------------------------------------------------
extern "C" void kernel_launch(void* const* d_in, const int* in_sizes, int n_in,
                              void* d_out, int out_size) {
    const float* x         = (const float*)d_in[0];
    const int*   eidx      = (const int*)d_in[1];
    const float* edge_attr = (const float*)d_in[2];
    const float* glob      = (const float*)d_in[3];
    const int*   batch     = (const int*)d_in[4];
    const float* W_e       = (const float*)d_in[5];
    const float* b_e       = (const float*)d_in[6];
    // d_in[7] = W_le, d_in[8] = b_le -- dead
    const float* W_n       = (const float*)d_in[9];
    const float* b_n       = (const float*)d_in[10];
    const float* W_n2      = (const float*)d_in[11];
    const float* b_n2      = (const float*)d_in[12];
    const float* W_g       = (const float*)d_in[13];
    const float* b_g       = (const float*)d_in[14];
    // d_in[15] = a -- dead

    const int N = in_sizes[0] / 128;
    const int E = in_sizes[1] / 2;
    const int B = in_sizes[3] / 64;

    float* xnew = (float*)d_out;               // [N,128]
    float* enew = xnew + (size_t)N * 128;      // [E,128]
    float* gnew = enew + (size_t)E * 128;      // [B,64]

    flags_zero_kernel<<<(N + 255) / 256, 256>>>(N);
    flags_set_kernel<<<(E + 255) / 256, 256>>>(eidx, E, N);
    precompute_kernel<<<129 + B, 128>>>(W_n, b_n, W_n2, b_n2, glob);
    node_kernel<<<(N + 63) / 64, 256>>>(x, W_e, b_e, batch, xnew, N, B);
    edge_kernel<<<((E + 63) / 64) * 2, 128>>>(edge_attr, eidx, W_e, enew, E, N);
    global_kernel<<<B, 128>>>(xnew, batch, glob, W_g, b_g, gnew, N);
}

// round 8
// speedup vs baseline: 1.5159x; 1.1406x over previous
#include <cuda_runtime.h>

// ---------------------------------------------------------------------------
// GATv2 block — algebraically reduced; edge GEMM on tensor cores (tf32 mma,
// no per-element cvt: A fed as raw fp32 (HW truncates to tf32), B pre-rounded
// once into d_Web).
//
// Identities:
//   Sum_e alpha_e = 1 per destination node with >=1 incoming edge, and agg
//   gathers nodes[R] (constant within a segment):
//     agg[n] = flag[n] * (x[n]@W_n + b_n)
//   x_new = relu( flag * (x@W_c + b_c) + G2[batch] )     (exact fp32)
//   e_new = relu( P[L] + edge_attr @ W_e[128:192] )       (tf32 mma + fp32 P)
//       P  = x@W_e[0:128] + b_e                           (exact fp32)
//   g_new = relu( [glob, segment_mean(x_new)] @ W_g + b_g )
// W_le, b_le, a are dead w.r.t. all outputs.
// ---------------------------------------------------------------------------

#define MAX_N 50000

__device__ __align__(16) float d_P[MAX_N * 128];   // x @ W_e_top + b_e
__device__ __align__(16) float d_Wc[128 * 128];    // W_n @ W_n2_top
__device__ __align__(16) float d_bc[128];          // b_n @ W_n2_top
__device__ __align__(16) float d_G2[64 * 128];     // glob @ W_n2_bot + b_n2
__device__ __align__(16) float d_Web[64 * 128];    // tf32(W_e rows 128..191)
__device__ int d_flags[MAX_N];

__device__ __forceinline__ int clampi(int v, int lo, int hi) {
    return v < lo ? lo : (v > hi ? hi : v);
}

__device__ __forceinline__ float to_tf32(float x) {
    float r;
    asm("cvt.rna.tf32.f32 %0, %1;" : "=f"(r) : "f"(x));
    return r;
}

// ---------------------------------------------------------------------------
__global__ void flags_zero_kernel(int n) {
    int i = blockIdx.x * blockDim.x + threadIdx.x;
    if (i < n) d_flags[i] = 0;
}

__global__ void flags_set_kernel(const int* __restrict__ eidx, int E, int N) {
    int e = blockIdx.x * blockDim.x + threadIdx.x;
    if (e < E) {
        int r = eidx[E + e];  // edge_index[1][e] (destination)
        if ((unsigned)r < (unsigned)N) d_flags[r] = 1;
    }
}

// grid = 128 (W_c rows) + 1 (b_c) + B (G2 rows) + 64 (d_Web rows); 128 thr
__global__ void precompute_kernel(const float* __restrict__ W_n,
                                  const float* __restrict__ b_n,
                                  const float* __restrict__ W_n2,
                                  const float* __restrict__ b_n2,
                                  const float* __restrict__ glob,
                                  const float* __restrict__ W_e, int nGraphs) {
    int blk = blockIdx.x;
    int j = threadIdx.x;  // 0..127
    if (blk < 128) {
        __shared__ float wr[128];
        wr[j] = W_n[blk * 128 + j];
        __syncthreads();
        float acc = 0.f;
#pragma unroll 8
        for (int k = 0; k < 128; ++k) acc = fmaf(wr[k], W_n2[k * 128 + j], acc);
        d_Wc[blk * 128 + j] = acc;
    } else if (blk == 128) {
        float acc = 0.f;
        for (int k = 0; k < 128; ++k) acc = fmaf(b_n[k], W_n2[k * 128 + j], acc);
        d_bc[j] = acc;
    } else if (blk < 129 + nGraphs) {
        int b = blk - 129;
        float acc = b_n2[j];
        for (int k = 0; k < 64; ++k)
            acc = fmaf(glob[b * 64 + k], W_n2[(128 + k) * 128 + j], acc);
        d_G2[b * 128 + j] = acc;
    } else {
        int r = blk - (129 + nGraphs);  // 0..63
        d_Web[r * 128 + j] = to_tf32(W_e[(128 + r) * 128 + j]);
    }
}

// ---------------------------------------------------------------------------
// Node kernel (exact fp32): per 64-node tile, (64x128)@(128x256) GEMM.
//   cols 0..127   -> P   -> d_P
//   cols 128..255 -> x_new epilogue (flag, +b_c, +G2[batch], relu)
__global__ __launch_bounds__(256) void node_kernel(
    const float* __restrict__ x, const float* __restrict__ W_e,
    const float* __restrict__ b_e, const int* __restrict__ batch,
    float* __restrict__ xnew, int nNodes, int nGraphs)
{
    __shared__ __align__(16) float xs[64 * 128];   // 32 KB
    const int tid = threadIdx.x;
    const int n0 = blockIdx.x * 64;

    const float4* x4 = reinterpret_cast<const float4*>(x);
    float4* xs4w = reinterpret_cast<float4*>(xs);
    for (int idx = tid; idx < 64 * 32; idx += 256) {
        int node = idx >> 5, kk = idx & 31;
        int gn = n0 + node;
        xs4w[idx] = (gn < nNodes) ? x4[(size_t)gn * 32 + kk]
                                  : make_float4(0.f, 0.f, 0.f, 0.f);
    }
    __syncthreads();

    const int r = tid >> 6;
    const int c = tid & 63;

    const float4* wp = (c < 32)
        ? reinterpret_cast<const float4*>(W_e) + c
        : reinterpret_cast<const float4*>(d_Wc) + (c - 32);

    float acc[16][4];
#pragma unroll
    for (int i = 0; i < 16; ++i) {
        acc[i][0] = 0.f; acc[i][1] = 0.f; acc[i][2] = 0.f; acc[i][3] = 0.f;
    }

    const float4* xs4 = reinterpret_cast<const float4*>(xs);  // [64][32]

#pragma unroll 4
    for (int k4 = 0; k4 < 32; ++k4) {
        float4 w0 = wp[(k4 * 4 + 0) * 32];
        float4 w1 = wp[(k4 * 4 + 1) * 32];
        float4 w2 = wp[(k4 * 4 + 2) * 32];
        float4 w3 = wp[(k4 * 4 + 3) * 32];
#pragma unroll
        for (int i = 0; i < 16; ++i) {
            float4 xv = xs4[(r * 16 + i) * 32 + k4];
            acc[i][0] = fmaf(xv.x, w0.x, acc[i][0]);
            acc[i][1] = fmaf(xv.x, w0.y, acc[i][1]);
            acc[i][2] = fmaf(xv.x, w0.z, acc[i][2]);
            acc[i][3] = fmaf(xv.x, w0.w, acc[i][3]);
            acc[i][0] = fmaf(xv.y, w1.x, acc[i][0]);
            acc[i][1] = fmaf(xv.y, w1.y, acc[i][1]);
            acc[i][2] = fmaf(xv.y, w1.z, acc[i][2]);
            acc[i][3] = fmaf(xv.y, w1.w, acc[i][3]);
            acc[i][0] = fmaf(xv.z, w2.x, acc[i][0]);
            acc[i][1] = fmaf(xv.z, w2.y, acc[i][1]);
            acc[i][2] = fmaf(xv.z, w2.z, acc[i][2]);
            acc[i][3] = fmaf(xv.z, w2.w, acc[i][3]);
            acc[i][0] = fmaf(xv.w, w3.x, acc[i][0]);
            acc[i][1] = fmaf(xv.w, w3.y, acc[i][1]);
            acc[i][2] = fmaf(xv.w, w3.z, acc[i][2]);
            acc[i][3] = fmaf(xv.w, w3.w, acc[i][3]);
        }
    }

    if (c < 32) {
        const float4 bev = reinterpret_cast<const float4*>(b_e)[c];
        float4* P4 = reinterpret_cast<float4*>(d_P);
#pragma unroll
        for (int i = 0; i < 16; ++i) {
            int gn = n0 + r * 16 + i;
            if (gn < nNodes) {
                P4[(size_t)gn * 32 + c] =
                    make_float4(acc[i][0] + bev.x, acc[i][1] + bev.y,
                                acc[i][2] + bev.z, acc[i][3] + bev.w);
            }
        }
    } else {
        const int cc = c - 32;
        const float4 bcv = reinterpret_cast<const float4*>(d_bc)[cc];
        const float4* G24 = reinterpret_cast<const float4*>(d_G2);
        float4* out4 = reinterpret_cast<float4*>(xnew);
#pragma unroll
        for (int i = 0; i < 16; ++i) {
            int gn = n0 + r * 16 + i;
            if (gn < nNodes) {
                int fl = d_flags[gn];
                int b = clampi(batch[gn], 0, nGraphs - 1);
                float4 g2 = G24[b * 32 + cc];
                float4 v;
                v.x = (fl ? acc[i][0] + bcv.x : 0.f) + g2.x;
                v.y = (fl ? acc[i][1] + bcv.y : 0.f) + g2.y;
                v.z = (fl ? acc[i][2] + bcv.z : 0.f) + g2.z;
                v.w = (fl ? acc[i][3] + bcv.w : 0.f) + g2.w;
                v.x = fmaxf(v.x, 0.f); v.y = fmaxf(v.y, 0.f);
                v.z = fmaxf(v.z, 0.f); v.w = fmaxf(v.w, 0.f);
                out4[(size_t)gn * 32 + cc] = v;
            }
        }
    }
}

// ---------------------------------------------------------------------------
// Edge kernel (tf32 mma, no cvt): e_new = relu(P[L] + edge_attr @ W_eb).
// Block = 64 edges x 128 cols, 256 threads (8 warps: 4 in m x 2 in n).
// Two n-passes of 64 cols over a reused B buffer (A loaded once per block).
// A fed to mma as raw fp32 (HW truncation to tf32); B pre-rounded (d_Web).
// smem: A[64][68] + B[64][72] + Ls = 36 KB (conflict-free fragment loads).
__global__ __launch_bounds__(256) void edge_kernel(
    const float* __restrict__ edge_attr, const int* __restrict__ eidx,
    float* __restrict__ enew, int E, int nNodes)
{
    __shared__ __align__(16) float es[64 * 68];   // 17408 B
    __shared__ __align__(16) float Ws[64 * 72];   // 18432 B
    __shared__ int Ls[64];

    const int tid = threadIdx.x;
    const int e0 = blockIdx.x * 64;

    if (tid < 64) {
        int ge = e0 + tid;
        Ls[tid] = (ge < E) ? clampi(eidx[ge], 0, nNodes - 1) : 0;
    }

    // A tile: 64 edges x 64 k, raw fp32, stride 68 (vectorized LDG->STS)
    const float4* ea4 = reinterpret_cast<const float4*>(edge_attr);
#pragma unroll
    for (int it = 0; it < 4; ++it) {
        int idx = tid + it * 256;            // 0..1023
        int e = idx >> 4, kk = idx & 15;
        int ge = e0 + e;
        float4 v = (ge < E) ? ea4[(size_t)ge * 16 + kk]
                            : make_float4(0.f, 0.f, 0.f, 0.f);
        *reinterpret_cast<float4*>(es + e * 68 + kk * 4) = v;
    }

    const int warp = tid >> 5;
    const int lane = tid & 31;
    const int wm = warp & 3;      // m group: rows [16*wm, 16*wm+16)
    const int wn = warp >> 2;     // n group: pass-local cols [32*wn, +32)
    const int qr = lane >> 2;     // 0..7
    const int qc = lane & 3;      // 0..3

    const float* arow0 = es + (wm * 16 + qr) * 68;
    const float* arow1 = arow0 + 8 * 68;
    const float4* Wg4 = reinterpret_cast<const float4*>(d_Web);

    const float2* P2 = reinterpret_cast<const float2*>(d_P);
    float2* out2 = reinterpret_cast<float2*>(enew);

#pragma unroll
    for (int h = 0; h < 2; ++h) {
        // B half: 64 k x 64 n (cols [64h, 64h+64)), pre-rounded tf32, stride 72
#pragma unroll
        for (int it = 0; it < 4; ++it) {
            int idx = tid + it * 256;        // 0..1023
            int k = idx >> 4, kk = idx & 15;
            float4 v = Wg4[k * 32 + h * 16 + kk];
            *reinterpret_cast<float4*>(Ws + k * 72 + kk * 4) = v;
        }
        __syncthreads();

        float c[4][4];
#pragma unroll
        for (int j = 0; j < 4; ++j) {
            c[j][0] = 0.f; c[j][1] = 0.f; c[j][2] = 0.f; c[j][3] = 0.f;
        }

#pragma unroll
        for (int s = 0; s < 8; ++s) {
            const int kb = s * 8;
            float a0 = arow0[kb + qc];
            float a1 = arow1[kb + qc];
            float a2 = arow0[kb + qc + 4];
            float a3 = arow1[kb + qc + 4];
            const float* b0p = Ws + (kb + qc) * 72 + wn * 32 + qr;
            const float* b1p = b0p + 4 * 72;
#pragma unroll
            for (int j = 0; j < 4; ++j) {
                float b0 = b0p[8 * j];
                float b1 = b1p[8 * j];
                asm volatile(
                    "mma.sync.aligned.m16n8k8.row.col.f32.tf32.tf32.f32 "
                    "{%0,%1,%2,%3}, {%4,%5,%6,%7}, {%8,%9}, {%0,%1,%2,%3};"
                    : "+f"(c[j][0]), "+f"(c[j][1]), "+f"(c[j][2]), "+f"(c[j][3])
                    : "r"(__float_as_uint(a0)), "r"(__float_as_uint(a1)),
                      "r"(__float_as_uint(a2)), "r"(__float_as_uint(a3)),
                      "r"(__float_as_uint(b0)), "r"(__float_as_uint(b1)));
            }
        }

        // Epilogue: + P[L], relu, store (cols for this pass only)
#pragma unroll
        for (int half = 0; half < 2; ++half) {
            int eloc = wm * 16 + qr + half * 8;
            int ge = e0 + eloc;
            if (ge < E) {
                int L = Ls[eloc];
                const float2* prow = P2 + (size_t)L * 64;
                float2* orow = out2 + (size_t)ge * 64;
#pragma unroll
                for (int j = 0; j < 4; ++j) {
                    int col = h * 64 + wn * 32 + 8 * j + qc * 2;
                    float2 p = prow[col >> 1];
                    float2 v;
                    v.x = fmaxf(c[j][half * 2 + 0] + p.x, 0.f);
                    v.y = fmaxf(c[j][half * 2 + 1] + p.y, 0.f);
                    orow[col >> 1] = v;
                }
            }
        }
        __syncthreads();   // B buffer reused next pass
    }
}

// ---------------------------------------------------------------------------
// Global kernel: one block (128 thr) per graph; batch sorted -> binary search.
__global__ void global_kernel(const float* __restrict__ xnew,
                              const int* __restrict__ batch,
                              const float* __restrict__ glob,
                              const float* __restrict__ W_g,
                              const float* __restrict__ b_g,
                              float* __restrict__ gout, int nNodes)
{
    const int b = blockIdx.x;
    const int tid = threadIdx.x;  // 128 threads

    int lo = 0, hi = nNodes;
    while (lo < hi) { int mid = (lo + hi) >> 1; if (batch[mid] < b) lo = mid + 1; else hi = mid; }
    int s = lo;
    lo = s; hi = nNodes;
    while (lo < hi) { int mid = (lo + hi) >> 1; if (batch[mid] < b + 1) lo = mid + 1; else hi = mid; }
    int e2 = lo;

    float sum = 0.f;
    for (int row = s; row < e2; ++row) sum += xnew[(size_t)row * 128 + tid];

    __shared__ float mean_s[128];
    __shared__ float glob_s[64];
    float cnt = fmaxf((float)(e2 - s), 1.0f);
    mean_s[tid] = sum / cnt;
    if (tid < 64) glob_s[tid] = glob[b * 64 + tid];
    __syncthreads();

    if (tid < 64) {
        float acc = b_g[tid];
        for (int k = 0; k < 64; ++k)  acc = fmaf(glob_s[k], W_g[k * 64 + tid], acc);
        for (int k = 0; k < 128; ++k) acc = fmaf(mean_s[k], W_g[(64 + k) * 64 + tid], acc);
        gout[b * 64 + tid] = fmaxf(acc, 0.f);
    }
}

// ---------------------------------------------------------------------------
extern "C" void kernel_launch(void* const* d_in, const int* in_sizes, int n_in,
                              void* d_out, int out_size) {
    const float* x         = (const float*)d_in[0];
    const int*   eidx      = (const int*)d_in[1];
    const float* edge_attr = (const float*)d_in[2];
    const float* glob      = (const float*)d_in[3];
    const int*   batch     = (const int*)d_in[4];
    const float* W_e       = (const float*)d_in[5];
    const float* b_e       = (const float*)d_in[6];
    // d_in[7] = W_le, d_in[8] = b_le -- dead
    const float* W_n       = (const float*)d_in[9];
    const float* b_n       = (const float*)d_in[10];
    const float* W_n2      = (const float*)d_in[11];
    const float* b_n2      = (const float*)d_in[12];
    const float* W_g       = (const float*)d_in[13];
    const float* b_g       = (const float*)d_in[14];
    // d_in[15] = a -- dead

    const int N = in_sizes[0] / 128;
    const int E = in_sizes[1] / 2;
    const int B = in_sizes[3] / 64;

    float* xnew = (float*)d_out;               // [N,128]
    float* enew = xnew + (size_t)N * 128;      // [E,128]
    float* gnew = enew + (size_t)E * 128;      // [B,64]

    flags_zero_kernel<<<(N + 255) / 256, 256>>>(N);
    flags_set_kernel<<<(E + 255) / 256, 256>>>(eidx, E, N);
    precompute_kernel<<<129 + B + 64, 128>>>(W_n, b_n, W_n2, b_n2, glob, W_e, B);
    node_kernel<<<(N + 63) / 64, 256>>>(x, W_e, b_e, batch, xnew, N, B);
    edge_kernel<<<(E + 63) / 64, 256>>>(edge_attr, eidx, enew, E, N);
    global_kernel<<<B, 128>>>(xnew, batch, glob, W_g, b_g, gnew, N);
}